// round 13
// baseline (speedup 1.0000x reference)
#include <cuda_runtime.h>

#define T_LEN 2048
typedef unsigned long long u64;

// ---- MUFU.TANH (1 MUFU per activation) ----
__device__ __forceinline__ float tanha(float x){ float y; asm("tanh.approx.f32 %0, %1;" : "=f"(y) : "f"(x)); return y; }

// ---- packed f32x2 helpers (sm_100+) ----
__device__ __forceinline__ u64 pk(float lo, float hi){ u64 d; asm("mov.b64 %0, {%1, %2};" : "=l"(d) : "f"(lo), "f"(hi)); return d; }
__device__ __forceinline__ void unpk(u64 d, float& lo, float& hi){ asm("mov.b64 {%0, %1}, %2;" : "=f"(lo), "=f"(hi) : "l"(d)); }
__device__ __forceinline__ u64 fma2_(u64 a, u64 b, u64 c){ u64 d; asm("fma.rn.f32x2 %0, %1, %2, %3;" : "=l"(d) : "l"(a), "l"(b), "l"(c)); return d; }
__device__ __forceinline__ u64 add2_(u64 a, u64 b){ u64 d; asm("add.rn.f32x2 %0, %1, %2;" : "=l"(d) : "l"(a), "l"(b)); return d; }

// Activation on pre-scaled preacts (sigmoid rows x0.5; h carried as 2h with
// the extra 0.5 folded into h-consuming weights). Returns 2h; updates c.
__device__ __forceinline__ float lstm_act(float a_i, float a_f, float a_g, float a_o, float& c) {
    const float thi = tanha(a_i), thf = tanha(a_f);
    const float thg = tanha(a_g), tho = tanha(a_o);
    const float F  = fmaf(0.5f, thf, 0.5f);
    const float g2 = fmaf(thi, thg, thg);           // 2*sigmoid(i)*tanh(g)
    c = fmaf(F, c, 0.5f * g2);
    const float thc = tanha(c);
    return fmaf(tho, thc, thc);                      // 2*sigmoid(o)*tanh(c)
}

// LAYER-SPLIT-ACROSS-LANES: 16 lanes per batch element.
//   lanes 0..7  (L1): lane j owns layer-1 unit j  -> produces h1_j
//   lanes 8..15 (L2): lane j owns layer-2 unit j  -> produces h2_j (1 step behind)
// Each lane computes its unit's FULL gate quad as two packed 17-term dots:
//   acc = fma2(WX, x, B) + sum_k W1[k]*H1[k] + sum_k W2[k]*H2[k]
// with W2=0 on L1 lanes and WX=0 on L2 lanes (warp stays convergent).
// Then ONE 5-tanh activation tower per lane — the two layers' towers run in
// PARALLEL lanes instead of back-to-back in program order (the R7-R11 wall).
// Exchange: store own h (2 STS.32, slot=g), syncwarp, reload 8 LDS.128.
__global__ void __launch_bounds__(128) lstm2_split_kernel(
    const float* __restrict__ x,
    const float* __restrict__ w_ih1, const float* __restrict__ w_hh1,
    const float* __restrict__ b_ih1, const float* __restrict__ b_hh1,
    const float* __restrict__ w_ih2, const float* __restrict__ w_hh2,
    const float* __restrict__ b_ih2, const float* __restrict__ b_hh2,
    const float* __restrict__ fc_w, const float* __restrict__ fc_b,
    float* __restrict__ out, int B)
{
    const int tid  = blockIdx.x * blockDim.x + threadIdx.x;
    const int pidx = tid >> 4;                 // batch element
    if (pidx >= B) return;
    const int g    = tid & 15;                 // lane within group
    const int j    = g & 7;                    // unit owned
    const bool L2  = (g >= 8);

    const int ri = j, rf = j + 8, rg = j + 16, ro = j + 24;

    // fold: sigmoid rows x0.5; h-consuming weights an extra x0.5 (h is 2h)
    const float SH = 0.25f, TH = 0.5f, SX = 0.5f, TX = 1.0f;

    // seg1 input is H1 for both layers: L1 lanes use w_hh1, L2 lanes use w_ih2
    const float* w1 = L2 ? w_ih2 : w_hh1;
    u64 W1IF[8], W1GO[8], W2IF[8], W2GO[8];
    #pragma unroll
    for (int k = 0; k < 8; k++) {
        W1IF[k] = pk(SH * w1[ri*8+k], SH * w1[rf*8+k]);
        W1GO[k] = pk(TH * w1[rg*8+k], SH * w1[ro*8+k]);
        // seg2 input is H2: only L2 lanes have real weights (w_hh2)
        W2IF[k] = L2 ? pk(SH * w_hh2[ri*8+k], SH * w_hh2[rf*8+k]) : 0ull;
        W2GO[k] = L2 ? pk(TH * w_hh2[rg*8+k], SH * w_hh2[ro*8+k]) : 0ull;
    }
    // x-term: only L1 lanes (w_ih1 is (32,1))
    const u64 WXIF = L2 ? 0ull : pk(SX * w_ih1[ri], SX * w_ih1[rf]);
    const u64 WXGO = L2 ? 0ull : pk(TX * w_ih1[rg], SX * w_ih1[ro]);
    const float* bi = L2 ? b_ih2 : b_ih1;
    const float* bh = L2 ? b_hh2 : b_hh1;
    const u64 BIF = pk(SX*(bi[ri]+bh[ri]), SX*(bi[rf]+bh[rf]));
    const u64 BGO = pk(TX*(bi[rg]+bh[rg]), SX*(bi[ro]+bh[ro]));

    // ---- SMEM h-exchange: [parity][group][h1: 0..7 | h2: 8..15 | pad], stride 18 ----
    __shared__ __align__(16) u64 hb[2][8][18];
    const int grp = threadIdx.x >> 4;          // group within CTA (0..7)

    float c = 0.0f;                            // c1_j (L1 lanes) or c2_j (L2 lanes)

    const float* xb = x + (size_t)pidx * T_LEN;

    // ---- prologue (t=0): L1 lanes compute h1(0); L2 lanes store h2(-1)=0 ----
    {
        const float x0 = __ldg(&xb[0]);
        float h0 = 0.0f;
        if (!L2) {
            float ai, af, ag, ao;
            unpk(fma2_(WXIF, pk(x0, x0), BIF), ai, af);
            unpk(fma2_(WXGO, pk(x0, x0), BGO), ag, ao);
            h0 = lstm_act(ai, af, ag, ao, c);
        }
        float* s = (float*)&hb[0][grp][g];     // slot = g (uniform)
        s[0] = h0; s[1] = h0;
        __syncwarp();
    }

    float xt_next = __ldg(&xb[1]);

    // ---- main loop: iter t -> L1 lanes produce h1(t), L2 lanes h2(t-1) ----
    #pragma unroll 2
    for (int t = 1; t < T_LEN; t++) {
        const float xt = xt_next;
        xt_next = __ldg(&xb[(t + 1) & (T_LEN - 1)]);   // wraps harmlessly
        const int q = (t - 1) & 1, p = t & 1;

        // reload h vectors: 8x LDS.128 (rows 16B-aligned, stride 144B)
        u64 H1[8], H2[8];
        {
            const ulonglong2* hv = (const ulonglong2*)&hb[q][grp][0];
            #pragma unroll
            for (int m = 0; m < 4; m++) { ulonglong2 v = hv[m];     H1[2*m] = v.x; H1[2*m+1] = v.y; }
            #pragma unroll
            for (int m = 0; m < 4; m++) { ulonglong2 v = hv[4 + m]; H2[2*m] = v.x; H2[2*m+1] = v.y; }
        }

        const u64 XT = pk(xt, xt);

        // gate quad: two packed 17-term dots, each split into two chains
        u64 aIF = fma2_(WXIF, XT, BIF);
        u64 aGO = fma2_(WXGO, XT, BGO);
        #pragma unroll
        for (int k = 0; k < 4; k++) {
            aIF = fma2_(W1IF[k], H1[k], aIF);
            aGO = fma2_(W1GO[k], H1[k], aGO);
        }
        #pragma unroll
        for (int k = 0; k < 4; k++) {
            aIF = fma2_(W2IF[k], H2[k], aIF);
            aGO = fma2_(W2GO[k], H2[k], aGO);
        }
        u64 bIF = fma2_(W1IF[4], H1[4], 0ull);
        u64 bGO = fma2_(W1GO[4], H1[4], 0ull);
        #pragma unroll
        for (int k = 5; k < 8; k++) {
            bIF = fma2_(W1IF[k], H1[k], bIF);
            bGO = fma2_(W1GO[k], H1[k], bGO);
        }
        #pragma unroll
        for (int k = 4; k < 8; k++) {
            bIF = fma2_(W2IF[k], H2[k], bIF);
            bGO = fma2_(W2GO[k], H2[k], bGO);
        }

        // ---- single activation tower (L1 and L2 towers run in parallel lanes) ----
        float a_i, a_f, a_g, a_o;
        unpk(add2_(aIF, bIF), a_i, a_f);
        unpk(add2_(aGO, bGO), a_g, a_o);
        const float hx = lstm_act(a_i, a_f, a_g, a_o, c);

        // ---- store own h (slot = g), one syncwarp ----
        float* s = (float*)&hb[p][grp][g];
        s[0] = hx; s[1] = hx;
        __syncwarp();
    }

    // ---- epilogue: one more step; only L2 lanes' result (h2(T-1)) matters ----
    float hlast;
    {
        u64 H1[8], H2[8];
        const ulonglong2* hv = (const ulonglong2*)&hb[1][grp][0];
        #pragma unroll
        for (int m = 0; m < 4; m++) { ulonglong2 v = hv[m];     H1[2*m] = v.x; H1[2*m+1] = v.y; }
        #pragma unroll
        for (int m = 0; m < 4; m++) { ulonglong2 v = hv[4 + m]; H2[2*m] = v.x; H2[2*m+1] = v.y; }

        u64 aIF = BIF, aGO = BGO;              // x-term irrelevant for L2 lanes
        #pragma unroll
        for (int k = 0; k < 8; k++) {
            aIF = fma2_(W1IF[k], H1[k], aIF);
            aGO = fma2_(W1GO[k], H1[k], aGO);
        }
        #pragma unroll
        for (int k = 0; k < 8; k++) {
            aIF = fma2_(W2IF[k], H2[k], aIF);
            aGO = fma2_(W2GO[k], H2[k], aGO);
        }
        float a_i, a_f, a_g, a_o;
        unpk(aIF, a_i, a_f);
        unpk(aGO, a_g, a_o);
        hlast = lstm_act(a_i, a_f, a_g, a_o, c);
    }

    // ---- fc: L2 lanes publish h2(T-1) (as 2h); lanes g<4 write out ----
    {
        float* s = (float*)&hb[0][grp][g];
        s[0] = hlast;                           // L1 lanes write garbage to 0..7 (unused)
        __syncwarp();
        if (g < 4) {
            float acc = fc_b[g];
            #pragma unroll
            for (int k = 0; k < 8; k++)
                acc = fmaf(0.5f * fc_w[g*8+k], ((const float*)&hb[0][grp][8 + k])[0], acc);
            out[pidx*4 + g] = acc;
        }
    }
}

extern "C" void kernel_launch(void* const* d_in, const int* in_sizes, int n_in,
                              void* d_out, int out_size)
{
    const float* x     = (const float*)d_in[0];
    const float* w_ih1 = (const float*)d_in[1];
    const float* w_hh1 = (const float*)d_in[2];
    const float* b_ih1 = (const float*)d_in[3];
    const float* b_hh1 = (const float*)d_in[4];
    const float* w_ih2 = (const float*)d_in[5];
    const float* w_hh2 = (const float*)d_in[6];
    const float* b_ih2 = (const float*)d_in[7];
    const float* b_hh2 = (const float*)d_in[8];
    const float* fc_w  = (const float*)d_in[9];
    const float* fc_b  = (const float*)d_in[10];
    float* out = (float*)d_out;

    const int B = in_sizes[0] / T_LEN;        // 4096
    const int threads = B * 16;               // 65536 -> 2048 warps (3.46/SMSP)
    const int block = 128;                    // 8 groups/CTA, 512 CTAs
    const int grid = (threads + block - 1) / block;

    lstm2_split_kernel<<<grid, block>>>(x, w_ih1, w_hh1, b_ih1, b_hh1,
                                        w_ih2, w_hh2, b_ih2, b_hh2,
                                        fc_w, fc_b, out, B);
}

// round 14
// speedup vs baseline: 1.4289x; 1.4289x over previous
#include <cuda_runtime.h>

#define T_LEN 2048
typedef unsigned long long u64;

// ---- MUFU.TANH (1 MUFU per activation) ----
__device__ __forceinline__ float tanha(float x){ float y; asm("tanh.approx.f32 %0, %1;" : "=f"(y) : "f"(x)); return y; }

// ---- packed f32x2 helpers (sm_100+) ----
__device__ __forceinline__ u64 pk(float lo, float hi){ u64 d; asm("mov.b64 %0, {%1, %2};" : "=l"(d) : "f"(lo), "f"(hi)); return d; }
__device__ __forceinline__ void unpk(u64 d, float& lo, float& hi){ asm("mov.b64 {%0, %1}, %2;" : "=f"(lo), "=f"(hi) : "l"(d)); }
__device__ __forceinline__ u64 fma2_(u64 a, u64 b, u64 c){ u64 d; asm("fma.rn.f32x2 %0, %1, %2, %3;" : "=l"(d) : "l"(a), "l"(b), "l"(c)); return d; }
__device__ __forceinline__ u64 mul2_(u64 a, u64 b){ u64 d; asm("mul.rn.f32x2 %0, %1, %2;" : "=l"(d) : "l"(a), "l"(b)); return d; }
__device__ __forceinline__ u64 add2_(u64 a, u64 b){ u64 d; asm("add.rn.f32x2 %0, %1, %2;" : "=l"(d) : "l"(a), "l"(b)); return d; }

// Activation on pre-scaled preacts (sigmoid rows x0.5; h carried as 2h with
// the extra 0.5 folded into h-consuming weights). Returns 2h; updates c.
__device__ __forceinline__ float lstm_act(float a_i, float a_f, float a_g, float a_o, float& c) {
    const float thi = tanha(a_i), thf = tanha(a_f);
    const float thg = tanha(a_g), tho = tanha(a_o);
    const float F  = fmaf(0.5f, thf, 0.5f);
    const float g2 = fmaf(thi, thg, thg);           // 2*sigmoid(i)*tanh(g)
    c = fmaf(F, c, 0.5f * g2);
    const float thc = tanha(c);
    return fmaf(tho, thc, thc);                      // 2*sigmoid(o)*tanh(c)
}

// PIPELINED-EXCHANGE version of the best kernel (R8/R10 layout):
// 8 lanes per batch; lane j owns gate rows {j,j+8,j+16,j+24} of both layers.
// The h exchange is software-pipelined INSIDE the step, barrier-free:
//   L1 dot -> L2 partial over H1 -> L1 tower -> STS h1 -> LDS H1'(next)
//   -> L2 partial over H2 -> L2 tower -> STS h2 -> LDS H2'(next)
// The warp is fully convergent and per-warp SMEM ops are program-ordered by
// the LSU, so no __syncwarp is needed in the loop; single buffer (WAR is
// protected by program order). h1's critical cycle drops to
// dot + tower + STS + LDS (~110 cyc); the whole L2 stream runs in the slack.
__global__ void __launch_bounds__(128) lstm2_pipe_kernel(
    const float* __restrict__ x,
    const float* __restrict__ w_ih1, const float* __restrict__ w_hh1,
    const float* __restrict__ b_ih1, const float* __restrict__ b_hh1,
    const float* __restrict__ w_ih2, const float* __restrict__ w_hh2,
    const float* __restrict__ b_ih2, const float* __restrict__ b_hh2,
    const float* __restrict__ fc_w, const float* __restrict__ fc_b,
    float* __restrict__ out, int B)
{
    const int tid = blockIdx.x * blockDim.x + threadIdx.x;
    const int b   = tid >> 3;
    if (b >= B) return;
    const int j   = tid & 7;
    const unsigned FULL = 0xffffffffu;

    const int gi = j, gf = j + 8, gg = j + 16, go = j + 24;

    // fold: sigmoid rows x0.5; h-consuming weights an extra x0.5 (h is 2h)
    const float SH = 0.25f, TH = 0.5f, SX = 0.5f, TX = 1.0f;

    u64 whIF1[8], whGO1[8], wxIF2[8], wxGO2[8], whIF2[8], whGO2[8];
    #pragma unroll
    for (int k = 0; k < 8; k++) {
        whIF1[k] = pk(SH * w_hh1[gi*8+k], SH * w_hh1[gf*8+k]);
        whGO1[k] = pk(TH * w_hh1[gg*8+k], SH * w_hh1[go*8+k]);
        wxIF2[k] = pk(SH * w_ih2[gi*8+k], SH * w_ih2[gf*8+k]);
        wxGO2[k] = pk(TH * w_ih2[gg*8+k], SH * w_ih2[go*8+k]);
        whIF2[k] = pk(SH * w_hh2[gi*8+k], SH * w_hh2[gf*8+k]);
        whGO2[k] = pk(TH * w_hh2[gg*8+k], SH * w_hh2[go*8+k]);
    }
    const u64 wx1IF = pk(SX * w_ih1[gi], SX * w_ih1[gf]);
    const u64 wx1GO = pk(TX * w_ih1[gg], SX * w_ih1[go]);
    const u64 bIF1  = pk(SX*(b_ih1[gi]+b_hh1[gi]), SX*(b_ih1[gf]+b_hh1[gf]));
    const u64 bGO1  = pk(TX*(b_ih1[gg]+b_hh1[gg]), SX*(b_ih1[go]+b_hh1[go]));
    const u64 bIF2  = pk(SX*(b_ih2[gi]+b_hh2[gi]), SX*(b_ih2[gf]+b_hh2[gf]));
    const u64 bGO2  = pk(TX*(b_ih2[gg]+b_hh2[gg]), SX*(b_ih2[go]+b_hh2[go]));

    // ---- SMEM h-exchange: single buffer [group][h1: 0..7 | h2: 8..15 | pad] ----
    __shared__ __align__(16) u64 hb[16][18];
    const int grp = threadIdx.x >> 3;         // group within CTA (0..15)

    float c1 = 0.0f, c2 = 0.0f;

    const float* xb = x + (size_t)b * T_LEN;

    u64 H1[8], H2[8];

    // ---- prologue (t=0): L1 step 0 (h1=c1=0); h2(-1)=0 ----
    {
        const float x0 = __ldg(&xb[0]);
        float ai, af, ag, ao;
        unpk(fma2_(wx1IF, pk(x0, x0), bIF1), ai, af);
        unpk(fma2_(wx1GO, pk(x0, x0), bGO1), ag, ao);
        const float h1x = lstm_act(ai, af, ag, ao, c1);
        hb[grp][j]     = pk(h1x, h1x);
        hb[grp][8 + j] = 0ull;
        __syncwarp();                          // once, outside the hot loop
        const ulonglong2* hv = (const ulonglong2*)&hb[grp][0];
        #pragma unroll
        for (int m = 0; m < 4; m++) { ulonglong2 v = hv[m];     H1[2*m] = v.x; H1[2*m+1] = v.y; }
        #pragma unroll
        for (int m = 0; m < 4; m++) { ulonglong2 v = hv[4 + m]; H2[2*m] = v.x; H2[2*m+1] = v.y; }
    }

    float xt_next = __ldg(&xb[1]);

    // ---- main loop: iteration t computes L1(t) and L2(t-1), pipelined ----
    #pragma unroll 2
    for (int t = 1; t < T_LEN; t++) {
        const float xt = xt_next;
        xt_next = __ldg(&xb[(t + 1) & (T_LEN - 1)]);   // wraps harmlessly
        const u64 XT = pk(xt, xt);

        // L1(t) pre-acts over H1 (two short chains - critical path)
        u64 aIF0 = fma2_(wx1IF, XT, bIF1);
        u64 aGO0 = fma2_(wx1GO, XT, bGO1);
        #pragma unroll
        for (int k = 0; k < 4; k++) {
            aIF0 = fma2_(whIF1[k], H1[k], aIF0);
            aGO0 = fma2_(whGO1[k], H1[k], aGO0);
        }
        u64 aIF1 = mul2_(whIF1[4], H1[4]);
        u64 aGO1 = mul2_(whGO1[4], H1[4]);
        #pragma unroll
        for (int k = 5; k < 8; k++) {
            aIF1 = fma2_(whIF1[k], H1[k], aIF1);
            aGO1 = fma2_(whGO1[k], H1[k], aGO1);
        }

        // L2(t-1) partial over H1 (slack work; H1 dead afterwards)
        u64 eIFa = fma2_(wxIF2[0], H1[0], bIF2);
        u64 eGOa = fma2_(wxGO2[0], H1[0], bGO2);
        #pragma unroll
        for (int k = 1; k < 8; k++) {
            eIFa = fma2_(wxIF2[k], H1[k], eIFa);
            eGOa = fma2_(wxGO2[k], H1[k], eGOa);
        }

        // L1 tower -> h1x, store, and IMMEDIATELY reload H1 for next step
        float a_i, a_f, a_g, a_o;
        unpk(add2_(aIF0, aIF1), a_i, a_f);
        unpk(add2_(aGO0, aGO1), a_g, a_o);
        const float h1x = lstm_act(a_i, a_f, a_g, a_o, c1);
        hb[grp][j] = pk(h1x, h1x);
        {
            const ulonglong2* hv = (const ulonglong2*)&hb[grp][0];
            #pragma unroll
            for (int m = 0; m < 4; m++) { ulonglong2 v = hv[m]; H1[2*m] = v.x; H1[2*m+1] = v.y; }
        }

        // L2(t-1) rest over H2 (H2 dead afterwards), tower, store, reload H2
        u64 eIFb = mul2_(whIF2[0], H2[0]);
        u64 eGOb = mul2_(whGO2[0], H2[0]);
        #pragma unroll
        for (int k = 1; k < 8; k++) {
            eIFb = fma2_(whIF2[k], H2[k], eIFb);
            eGOb = fma2_(whGO2[k], H2[k], eGOb);
        }
        float e_i, e_f, e_g, e_o;
        unpk(add2_(eIFa, eIFb), e_i, e_f);
        unpk(add2_(eGOa, eGOb), e_g, e_o);
        const float h2x = lstm_act(e_i, e_f, e_g, e_o, c2);
        hb[grp][8 + j] = pk(h2x, h2x);
        {
            const ulonglong2* hv = (const ulonglong2*)&hb[grp][0];
            #pragma unroll
            for (int m = 0; m < 4; m++) { ulonglong2 v = hv[4 + m]; H2[2*m] = v.x; H2[2*m+1] = v.y; }
        }
    }

    // ---- epilogue: L2(T-1) from H1 = h1(T-1), H2 = h2(T-2) ----
    float h2last;
    {
        u64 eIFa = fma2_(wxIF2[0], H1[0], bIF2);
        u64 eGOa = fma2_(wxGO2[0], H1[0], bGO2);
        #pragma unroll
        for (int k = 1; k < 8; k++) {
            eIFa = fma2_(wxIF2[k], H1[k], eIFa);
            eGOa = fma2_(wxGO2[k], H1[k], eGOa);
        }
        u64 eIFb = mul2_(whIF2[0], H2[0]);
        u64 eGOb = mul2_(whGO2[0], H2[0]);
        #pragma unroll
        for (int k = 1; k < 8; k++) {
            eIFb = fma2_(whIF2[k], H2[k], eIFb);
            eGOb = fma2_(whGO2[k], H2[k], eGOb);
        }
        float e_i, e_f, e_g, e_o;
        unpk(add2_(eIFa, eIFb), e_i, e_f);
        unpk(add2_(eGOa, eGOb), e_g, e_o);
        h2last = lstm_act(e_i, e_f, e_g, e_o, c2);    // h2x of final step
    }

    // ---- fc on final h2 (h stored as 2h -> fc_w pre-halved) ----
    float h2f[8];
    #pragma unroll
    for (int k = 0; k < 8; k++) h2f[k] = __shfl_sync(FULL, h2last, k, 8);
    if (j < 4) {
        float acc = fc_b[j];
        #pragma unroll
        for (int k = 0; k < 8; k++) acc = fmaf(0.5f * fc_w[j*8+k], h2f[k], acc);
        out[b*4 + j] = acc;
    }
}

extern "C" void kernel_launch(void* const* d_in, const int* in_sizes, int n_in,
                              void* d_out, int out_size)
{
    const float* x     = (const float*)d_in[0];
    const float* w_ih1 = (const float*)d_in[1];
    const float* w_hh1 = (const float*)d_in[2];
    const float* b_ih1 = (const float*)d_in[3];
    const float* b_hh1 = (const float*)d_in[4];
    const float* w_ih2 = (const float*)d_in[5];
    const float* w_hh2 = (const float*)d_in[6];
    const float* b_ih2 = (const float*)d_in[7];
    const float* b_hh2 = (const float*)d_in[8];
    const float* fc_w  = (const float*)d_in[9];
    const float* fc_b  = (const float*)d_in[10];
    float* out = (float*)d_out;

    const int B = in_sizes[0] / T_LEN;      // 4096
    const int threads = B * 8;              // 8 lanes per batch element
    const int block = 128;                  // best-known config
    const int grid = (threads + block - 1) / block;

    lstm2_pipe_kernel<<<grid, block>>>(x, w_ih1, w_hh1, b_ih1, b_hh1,
                                       w_ih2, w_hh2, b_ih2, b_hh2,
                                       fc_w, fc_b, out, B);
}